// round 4
// baseline (speedup 1.0000x reference)
#include <cuda_runtime.h>
#include <cuda_bf16.h>
#include <cstdint>

// ---------------------------------------------------------------------------
// Problem constants
// ---------------------------------------------------------------------------
#define N_TOK   65536          // b*n = 16*4096
#define C_CODES 2048
#define D       64
#define DP      68             // padded dim: [e | e^2 | 0 0 0]
#define DP4     17             // float4 per padded row
#define ROWS    128            // rows per CTA in argmin kernel
#define CC      64             // codes per chunk
#define NCHUNK  (C_CODES / CC) // 32
#define NTHREADS 256

#define DECAY_F 0.8f
#define OMD_F   0.2f           // 1.0 - 0.8 computed in double -> 0.2f
#define EPS_F   1e-5f

// Output layout (floats), concatenated in reference return order
#define OFF_Q    0                       // quantize        (16,4096,64) = 4194304
#define OFF_IND  4194304                 // embed_ind       (16,4096)    = 65536
#define OFF_NE   4259840                 // new_embeddings  (1,2048,64)  = 131072
#define OFF_NCS  4390912                 // new_cluster_size(1,2048)     = 2048
#define OFF_NEA  4392960                 // new_embed_avg   (1,2048,64)  = 131072

// ---------------------------------------------------------------------------
// Device scratch (static globals — no allocation)
// ---------------------------------------------------------------------------
__device__ float g_eext[C_CODES * DP];   // extended codebook [e(64) | e2 | 0 0 0]
__device__ int   g_ind[N_TOK];           // argmin index per row
__device__ float g_counts[C_CODES];
__device__ float g_sum[C_CODES * D];

// ---------------------------------------------------------------------------
// Helpers
// ---------------------------------------------------------------------------
__device__ __forceinline__ unsigned long long ffma2(unsigned long long a,
                                                    unsigned long long b,
                                                    unsigned long long c) {
    unsigned long long d;
    asm("fma.rn.f32x2 %0, %1, %2, %3;" : "=l"(d) : "l"(a), "l"(b), "l"(c));
    return d;
}

__device__ __forceinline__ void cp_async16(float* smem_dst, const float* gsrc) {
    unsigned s = (unsigned)__cvta_generic_to_shared(smem_dst);
    asm volatile("cp.async.cg.shared.global [%0], [%1], 16;\n" :: "r"(s), "l"(gsrc));
}
__device__ __forceinline__ void cp_async_commit() {
    asm volatile("cp.async.commit_group;\n" ::: "memory");
}
template <int NN>
__device__ __forceinline__ void cp_async_wait() {
    asm volatile("cp.async.wait_group %0;\n" :: "n"(NN) : "memory");
}

// ---------------------------------------------------------------------------
// K_zero: clear counts + sums (must happen every launch; graph replays)
// ---------------------------------------------------------------------------
__global__ void k_zero() {
    int i = blockIdx.x * blockDim.x + threadIdx.x;
    if (i < C_CODES) g_counts[i] = 0.0f;
    if (i < C_CODES * D) g_sum[i] = 0.0f;
}

// ---------------------------------------------------------------------------
// K_prep: build extended codebook rows [e, e^2, 0,0,0]. One warp per code.
// ---------------------------------------------------------------------------
__global__ void k_prep(const float* __restrict__ emb) {
    int w = (blockIdx.x * blockDim.x + threadIdx.x) >> 5;
    int lane = threadIdx.x & 31;
    if (w >= C_CODES) return;
    float2 v = *(const float2*)(emb + w * D + lane * 2);
    float sq = v.x * v.x + v.y * v.y;
    #pragma unroll
    for (int m = 16; m >= 1; m >>= 1)
        sq += __shfl_xor_sync(0xFFFFFFFFu, sq, m);
    *(float2*)(g_eext + w * DP + lane * 2) = v;
    if (lane == 0) {
        g_eext[w * DP + 64] = sq;
        g_eext[w * DP + 65] = 0.0f;
        g_eext[w * DP + 66] = 0.0f;
        g_eext[w * DP + 67] = 0.0f;
    }
}

// ---------------------------------------------------------------------------
// K_argmin: fused distance-GEMM + per-row argmin.
//   score(r,c) = e2[c] - 2*dot(x[r],e[c]) == dot(x''[r], e''[c])
//   x'' = [-2x, 1, 0,0,0],  e'' = [e, e2, 0,0,0]   (dim 68)
//   Accumulated with packed fp32x2 FMAs (even/odd k lanes), fp32-exact.
// Thread map: tx = tid&15 (codes, stride-16 interleave), ty = tid>>4 (rows).
// Micro-tile per thread: 8 rows x 4 codes.
// ---------------------------------------------------------------------------
__device__ __forceinline__ void issue_chunk(float* esbuf, const float* gsrc, int tid) {
    #pragma unroll
    for (int it = 0; it < 5; it++) {
        int idx = tid + it * NTHREADS;            // over CC*DP4 = 1088 float4s
        if (idx < CC * DP4) {
            int c = idx / DP4;
            int q = idx - c * DP4;
            cp_async16(esbuf + c * DP + 4 * q, gsrc + c * DP + 4 * q);
        }
    }
}

extern __shared__ float sm_dyn[];

__global__ __launch_bounds__(NTHREADS, 2)
void k_argmin(const float* __restrict__ x) {
    float* xs = sm_dyn;                       // ROWS * DP
    float* es = sm_dyn + ROWS * DP;           // 2 * CC * DP (double buffer)

    int tid = threadIdx.x;
    int row0 = blockIdx.x * ROWS;

    // Prefetch chunk 0 into buffer 0
    issue_chunk(es, g_eext, tid);
    cp_async_commit();

    // Load x tile, transformed to -2x, append [1,0,0,0]
    for (int idx = tid; idx < ROWS * (D / 4); idx += NTHREADS) {
        int r = idx >> 4, q = idx & 15;
        float4 v = *(const float4*)(x + (size_t)(row0 + r) * D + 4 * q);
        float4 w = make_float4(-2.0f * v.x, -2.0f * v.y, -2.0f * v.z, -2.0f * v.w);
        *(float4*)(xs + r * DP + 4 * q) = w;
    }
    for (int r = tid; r < ROWS; r += NTHREADS) {
        xs[r * DP + 64] = 1.0f;
        xs[r * DP + 65] = 0.0f;
        xs[r * DP + 66] = 0.0f;
        xs[r * DP + 67] = 0.0f;
    }

    int tx = tid & 15;
    int ty = tid >> 4;

    float best[8];
    int   bidx[8];
    #pragma unroll
    for (int i = 0; i < 8; i++) { best[i] = 3.4e38f; bidx[i] = 0; }

    for (int ch = 0; ch < NCHUNK; ch++) {
        int buf = ch & 1;
        if (ch + 1 < NCHUNK) {
            issue_chunk(es + (buf ^ 1) * CC * DP,
                        g_eext + (size_t)(ch + 1) * CC * DP, tid);
            cp_async_commit();
            cp_async_wait<1>();
        } else {
            cp_async_wait<0>();
        }
        __syncthreads();

        const float* eb = es + buf * CC * DP;

        unsigned long long acc[8][4];
        #pragma unroll
        for (int i = 0; i < 8; i++)
            #pragma unroll
            for (int j = 0; j < 4; j++) acc[i][j] = 0ULL;

        #pragma unroll
        for (int kq = 0; kq < DP4; kq++) {
            ulonglong2 ef[4];
            #pragma unroll
            for (int j = 0; j < 4; j++)
                ef[j] = *(const ulonglong2*)(eb + (tx + 16 * j) * DP + 4 * kq);
            #pragma unroll
            for (int i = 0; i < 8; i++) {
                ulonglong2 xf = *(const ulonglong2*)(xs + (ty + 16 * i) * DP + 4 * kq);
                #pragma unroll
                for (int j = 0; j < 4; j++) {
                    acc[i][j] = ffma2(xf.x, ef[j].x, acc[i][j]);
                    acc[i][j] = ffma2(xf.y, ef[j].y, acc[i][j]);
                }
            }
        }

        int cbase = ch * CC;
        #pragma unroll
        for (int i = 0; i < 8; i++) {
            #pragma unroll
            for (int j = 0; j < 4; j++) {
                float lo = __uint_as_float((unsigned)(acc[i][j] & 0xFFFFFFFFULL));
                float hi = __uint_as_float((unsigned)(acc[i][j] >> 32));
                float s = lo + hi;
                int c = cbase + tx + 16 * j;
                if (s < best[i]) { best[i] = s; bidx[i] = c; }
            }
        }
        __syncthreads();
    }

    // Reduce across the 16 tx lanes holding the same rows (width-16 butterfly).
    // Tie-break to the LOWER index to match argmax-first-occurrence semantics.
    #pragma unroll
    for (int i = 0; i < 8; i++) {
        float s = best[i];
        int   b = bidx[i];
        #pragma unroll
        for (int m = 8; m >= 1; m >>= 1) {
            float so = __shfl_xor_sync(0xFFFFFFFFu, s, m, 16);
            int   bo = __shfl_xor_sync(0xFFFFFFFFu, b, m, 16);
            if (so < s || (so == s && bo < b)) { s = so; b = bo; }
        }
        if (tx == 0) g_ind[row0 + ty + 16 * i] = b;
    }
}

// ---------------------------------------------------------------------------
// K_scatter: gather quantize + write embed_ind + scatter-add counts/sums.
// One warp per row; lanes split d.
// ---------------------------------------------------------------------------
__global__ void k_scatter(const float* __restrict__ x,
                          const float* __restrict__ emb,
                          float* __restrict__ out) {
    int row  = (blockIdx.x * blockDim.x + threadIdx.x) >> 5;
    int lane = threadIdx.x & 31;
    if (row >= N_TOK) return;
    int idx = g_ind[row];

    float2 q = *(const float2*)(emb + (size_t)idx * D + lane * 2);
    *(float2*)(out + OFF_Q + (size_t)row * D + lane * 2) = q;

    float2 xv = *(const float2*)(x + (size_t)row * D + lane * 2);
    atomicAdd(g_sum + (size_t)idx * D + lane * 2,     xv.x);
    atomicAdd(g_sum + (size_t)idx * D + lane * 2 + 1, xv.y);

    if (lane == 0) {
        atomicAdd(g_counts + idx, 1.0f);
        out[OFF_IND + row] = (float)idx;
    }
}

// ---------------------------------------------------------------------------
// K_final: EMA updates + laplace smoothing + renormalize. One CTA.
// ---------------------------------------------------------------------------
__global__ __launch_bounds__(1024)
void k_final(const float* __restrict__ cs,
             const float* __restrict__ ea,
             float* __restrict__ out) {
    __shared__ float s_ncs[C_CODES];
    __shared__ float s_red[32];
    int tid = threadIdx.x;

    float local = 0.0f;
    for (int c = tid; c < C_CODES; c += 1024) {
        float v = cs[c] * DECAY_F + g_counts[c] * OMD_F;
        s_ncs[c] = v;
        out[OFF_NCS + c] = v;
        local += v;
    }
    #pragma unroll
    for (int m = 16; m >= 1; m >>= 1)
        local += __shfl_xor_sync(0xFFFFFFFFu, local, m);
    if ((tid & 31) == 0) s_red[tid >> 5] = local;
    __syncthreads();
    if (tid < 32) {
        float v = s_red[tid];
        #pragma unroll
        for (int m = 16; m >= 1; m >>= 1)
            v += __shfl_xor_sync(0xFFFFFFFFu, v, m);
        if (tid == 0) s_red[0] = v;
    }
    __syncthreads();
    float tot   = s_red[0];
    float denom = tot + (float)C_CODES * EPS_F;

    for (int i = tid; i < C_CODES * D; i += 1024) {
        int c = i >> 6;
        float nea = ea[i] * DECAY_F + g_sum[i] * OMD_F;
        out[OFF_NEA + i] = nea;
        float sm = (s_ncs[c] + EPS_F) / denom * tot;
        out[OFF_NE + i] = nea / sm;
    }
}

// ---------------------------------------------------------------------------
// kernel_launch
// ---------------------------------------------------------------------------
extern "C" void kernel_launch(void* const* d_in, const int* in_sizes, int n_in,
                              void* d_out, int out_size) {
    (void)in_sizes; (void)n_in; (void)out_size;
    const float* x   = (const float*)d_in[0];
    const float* emb = (const float*)d_in[1];
    const float* cs  = (const float*)d_in[2];
    const float* ea  = (const float*)d_in[3];
    float* out = (float*)d_out;

    const int smem_bytes = (ROWS * DP + 2 * CC * DP) * (int)sizeof(float); // 69632
    cudaFuncSetAttribute(k_argmin, cudaFuncAttributeMaxDynamicSharedMemorySize,
                         smem_bytes);

    k_zero<<<(C_CODES * D + 255) / 256, 256>>>();
    k_prep<<<(C_CODES * 32 + 255) / 256, 256>>>(emb);
    k_argmin<<<N_TOK / ROWS, NTHREADS, smem_bytes>>>(x);
    k_scatter<<<(N_TOK * 32) / 256, 256>>>(x, emb, out);
    k_final<<<1, 1024>>>(cs, ea, out);
}